// round 5
// baseline (speedup 1.0000x reference)
#include <cuda_runtime.h>
#include <cuda_bf16.h>
#include <math.h>
#include <cstdint>

#define L_ 512
#define B_ 64
#define E_ 256
#define H_ 256
#define T_ 12

typedef unsigned long long u64;

// ---------------- helpers ----------------
__device__ __forceinline__ u64 fma2(u64 a, u64 b, u64 c) {
    u64 d;
    asm("fma.rn.f32x2 %0, %1, %2, %3;" : "=l"(d) : "l"(a), "l"(b), "l"(c));
    return d;
}
__device__ __forceinline__ float2 unpack2(u64 v) {
    float2 r;
    asm("mov.b64 {%0, %1}, %2;" : "=f"(r.x), "=f"(r.y) : "l"(v));
    return r;
}
__device__ __forceinline__ void st_release(int* p, int v) {
    asm volatile("st.release.gpu.global.b32 [%0], %1;" :: "l"(p), "r"(v) : "memory");
}
__device__ __forceinline__ int ld_acquire(const int* p) {
    int v;
    asm volatile("ld.acquire.gpu.global.b32 %0, [%1];" : "=r"(v) : "l"(p) : "memory");
    return v;
}
__device__ __forceinline__ float tanhap(float x) {
    float y;
    asm("tanh.approx.f32 %0, %1;" : "=f"(y) : "f"(x));
    return y;
}
__device__ __forceinline__ float sigap(float x) {
    return fmaf(0.5f, tanhap(0.5f * x), 0.5f);
}
__device__ __forceinline__ uint32_t smem_u32(const void* p) {
    uint32_t a;
    asm("{ .reg .u64 t; cvta.to.shared.u64 t, %1; cvt.u32.u64 %0, t; }" : "=r"(a) : "l"(p));
    return a;
}
__device__ __forceinline__ uint32_t packbf(float lo, float hi) {
    uint32_t r;
    asm("cvt.rn.bf16x2.f32 %0, %1, %2;" : "=r"(r) : "f"(hi), "f"(lo));
    return r;
}
__device__ __forceinline__ void ldsm_x4(uint32_t& r0, uint32_t& r1, uint32_t& r2, uint32_t& r3, uint32_t addr) {
    asm volatile("ldmatrix.sync.aligned.m8n8.x4.shared.b16 {%0,%1,%2,%3}, [%4];"
        : "=r"(r0), "=r"(r1), "=r"(r2), "=r"(r3) : "r"(addr));
}
__device__ __forceinline__ void mma16816(float& d0, float& d1, float& d2, float& d3,
                                         uint32_t a0, uint32_t a1, uint32_t a2, uint32_t a3,
                                         uint32_t b0, uint32_t b1) {
    asm volatile("mma.sync.aligned.m16n8k16.row.col.f32.bf16.bf16.f32 "
        "{%0,%1,%2,%3}, {%4,%5,%6,%7}, {%8,%9}, {%0,%1,%2,%3};"
        : "+f"(d0), "+f"(d1), "+f"(d2), "+f"(d3)
        : "r"(a0), "r"(a1), "r"(a2), "r"(a3), "r"(b0), "r"(b1));
}

// ---------------- scratch ----------------
__device__ float g_gx[(size_t)2*L_*B_*1024];   // input gates (incl bias): [2][L][B][4H]
__device__ float g_h [(size_t)2*L_*B_*H_];     // hidden states: [2][L][B][H] fp32
__device__ float g_emit[(size_t)L_*B_*T_];
__device__ float g_nll[B_];
__device__ int   g_cnt[16];                    // [dir 2][producer 8]

__global__ void k_reset() {
    int i = threadIdx.x;
    if (i < 16) g_cnt[i] = 0;
}

// ---------------- input-gate GEMM (f32x2 packed, unchanged from R3) ----------------
__global__ __launch_bounds__(256, 1) void k_ingate(
    const int* __restrict__ sent, const float* __restrict__ emb,
    const float* __restrict__ Wf, const float* __restrict__ bfv,
    const float* __restrict__ Wb, const float* __restrict__ bbv)
{
    extern __shared__ float Xs[];
    __shared__ int tok[B_];
    int l   = blockIdx.x;
    int tid = threadIdx.x;
    if (tid < B_) tok[tid] = sent[tid*L_ + l];
    __syncthreads();
    float4* Xs4 = (float4*)Xs;
    #pragma unroll
    for (int i = 0; i < 16; i++) {
        int e = i*256 + tid;
        int r = e >> 6, kq = e & 63;
        Xs4[e] = ((const float4*)emb)[(size_t)tok[r]*64 + kq];
    }
    __syncthreads();

    int j   = blockIdx.y*256 + tid;
    int dir = j >> 10, jj = j & 1023;
    const float* W = dir ? Wb : Wf;
    const ulonglong2* W2 = (const ulonglong2*)(W + (size_t)jj*256);
    const ulonglong2* X2 = (const ulonglong2*)Xs;

    u64 acc2[64];
    #pragma unroll
    for (int r = 0; r < 64; r++) acc2[r] = 0ull;

    #pragma unroll 1
    for (int k4 = 0; k4 < 64; k4++) {
        ulonglong2 w = W2[k4];
        #pragma unroll
        for (int r = 0; r < 64; r++) {
            ulonglong2 x = X2[r*64 + k4];
            acc2[r] = fma2(w.x, x.x, acc2[r]);
            acc2[r] = fma2(w.y, x.y, acc2[r]);
        }
    }
    float bias = (dir ? bbv : bfv)[jj];
    float* outp = g_gx + (((size_t)dir*L_ + l)*B_)*1024 + jj;
    #pragma unroll
    for (int r = 0; r < 64; r++) {
        float2 p = unpack2(acc2[r]);
        outp[(size_t)r*1024] = p.x + p.y + bias;
    }
}

// ---------------- persistent LSTM recurrence on mma.sync (bf16 HMMA) ----------------
// 16 CTAs: cid>>3 = dir, p = cid&7 owns hids [32p, 32p+32).
// D[128 gate-rows, 64 batch] = W_local[128,256] x h[64,256]^T
//   gate-row r: gate = r>>5, hid = hb + (r&31)
// A (W) bf16 fragments preloaded in registers (static).
// B (h) restaged to smem bf16 [64][264 halves] each step; ldmatrix.x4 loads.
// Epilogue: Ps[128][66] fp32 = gx (coalesced prefill) + D (RMW add),
//           then per-(hid,batch) gate quadruple -> activations -> h fp32.
static const int BS_PITCH_B = 528;              // 264 halves per row
static const int SM_PS      = 64 * BS_PITCH_B;  // 33792
static const int LSTM_SMEM  = SM_PS + 128*66*4; // 33792 + 33792 = 67584

__global__ __launch_bounds__(256, 1) void k_lstm(const float* __restrict__ Whf,
                                                 const float* __restrict__ Whb)
{
    extern __shared__ __align__(1024) char sm[];
    float* Ps = (float*)(sm + SM_PS);
    uint32_t smb = smem_u32(sm);
    int cid = blockIdx.x;
    int d = cid >> 3, p = cid & 7;
    int hb = p * 32;
    int tid = threadIdx.x;
    int w = tid >> 5, l = tid & 31;
    const float* W = d ? Whb : Whf;

    // ---- A fragments (static W) in registers ----
    int r0 = 16*w + (l >> 2), r1 = r0 + 8;
    const float* wr0 = W + (size_t)((r0 >> 5)*H_ + hb + (r0 & 31))*H_;
    const float* wr1 = W + (size_t)((r1 >> 5)*H_ + hb + (r1 & 31))*H_;
    uint32_t A0[16], A1[16], A2[16], A3[16];
    {
        int kc0 = (l & 3)*2;
        #pragma unroll
        for (int kt = 0; kt < 16; kt++) {
            int kc = kt*16 + kc0;
            A0[kt] = packbf(wr0[kc],   wr0[kc+1]);
            A1[kt] = packbf(wr1[kc],   wr1[kc+1]);
            A2[kt] = packbf(wr0[kc+8], wr0[kc+9]);
            A3[kt] = packbf(wr1[kc+8], wr1[kc+9]);
        }
    }

    // ---- ldmatrix per-lane row base addresses (one per n-tile) ----
    uint32_t rowa[8];
    {
        int lrow = l & 7, grp = l >> 3;
        #pragma unroll
        for (int nt = 0; nt < 8; nt++)
            rowa[nt] = smb + (uint32_t)((nt*8 + lrow)*BS_PITCH_B + grp*16);
    }

    // gx->Ps mapping (coalesced: lanes cover 32 consecutive gate-rows of one gate)
    int rr  = tid & 127;
    int bb0 = (tid >> 7) * 32;
    int goff = (rr >> 5)*256 + hb + (rr & 31);

    // phase-B mapping: thread owns (hid hl, batches 8*q8..8*q8+7)
    int hl = tid & 31, q8 = tid >> 5;
    float cst[8];
    #pragma unroll
    for (int k = 0; k < 8; k++) cst[k] = 0.f;

    int* my_cnt = g_cnt + d*8 + p;

    for (int s = 0; s < L_; s++) {
        int t = d ? (L_-1-s) : s;

        // ---- stage h (bf16) into Bs ----
        if (s == 0) {
            for (int i = tid; i < SM_PS/4; i += 256) ((uint32_t*)sm)[i] = 0;
        } else {
            if (tid < 8) {
                const int* fp = g_cnt + d*8 + tid;
                while (ld_acquire(fp) < s) { }
            }
            __syncthreads();
            int tprev = d ? (t+1) : (t-1);
            const float4* hsrc = (const float4*)(g_h + (((size_t)d*L_ + tprev)*B_)*H_);
            #pragma unroll
            for (int i = 0; i < 16; i++) {
                int idx = i*256 + tid;
                int b = idx >> 6, kq = idx & 63;
                float4 hv = hsrc[idx];
                uint2 v = make_uint2(packbf(hv.x, hv.y), packbf(hv.z, hv.w));
                *(uint2*)(sm + b*BS_PITCH_B + kq*8) = v;
            }
        }

        // ---- gx -> Ps (prefill with input-gate contribution) ----
        {
            const float* gxt = g_gx + ((size_t)(d*L_ + t)*B_)*1024 + goff;
            float* prow = Ps + rr*66 + bb0;
            #pragma unroll 8
            for (int j = 0; j < 32; j++)
                prow[j] = gxt[(size_t)(bb0 + j)*1024];
        }
        __syncthreads();

        // ---- MMA mainloop: D[128,64] ----
        float acc[8][4];
        #pragma unroll
        for (int nt = 0; nt < 8; nt++)
            #pragma unroll
            for (int k = 0; k < 4; k++) acc[nt][k] = 0.f;

        #pragma unroll
        for (int ktp = 0; ktp < 8; ktp++) {
            #pragma unroll
            for (int nt = 0; nt < 8; nt++) {
                uint32_t b0, b1, b2, b3;
                ldsm_x4(b0, b1, b2, b3, rowa[nt] + ktp*64);
                mma16816(acc[nt][0], acc[nt][1], acc[nt][2], acc[nt][3],
                         A0[2*ktp], A1[2*ktp], A2[2*ktp], A3[2*ktp], b0, b1);
                mma16816(acc[nt][0], acc[nt][1], acc[nt][2], acc[nt][3],
                         A0[2*ktp+1], A1[2*ktp+1], A2[2*ktp+1], A3[2*ktp+1], b2, b3);
            }
        }

        // ---- add D into Ps ----
        {
            int cc = (l & 3)*2;
            #pragma unroll
            for (int nt = 0; nt < 8; nt++) {
                float2* p0 = (float2*)(Ps + r0*66 + nt*8 + cc);
                float2 v0 = *p0; v0.x += acc[nt][0]; v0.y += acc[nt][1]; *p0 = v0;
                float2* p1 = (float2*)(Ps + r1*66 + nt*8 + cc);
                float2 v1 = *p1; v1.x += acc[nt][2]; v1.y += acc[nt][3]; *p1 = v1;
            }
        }
        __syncthreads();

        // ---- phase B: activations, c update, h out ----
        float hout[8];
        #pragma unroll
        for (int j = 0; j < 4; j++) {
            float2 vi = *(const float2*)(Ps + ( 0 + hl)*66 + q8*8 + 2*j);
            float2 vf = *(const float2*)(Ps + (32 + hl)*66 + q8*8 + 2*j);
            float2 vg = *(const float2*)(Ps + (64 + hl)*66 + q8*8 + 2*j);
            float2 vo = *(const float2*)(Ps + (96 + hl)*66 + q8*8 + 2*j);
            {
                float ig = sigap(vi.x), fg = sigap(vf.x), gg = tanhap(vg.x), og = sigap(vo.x);
                cst[2*j] = fg*cst[2*j] + ig*gg;
                hout[2*j] = og * tanhap(cst[2*j]);
            }
            {
                float ig = sigap(vi.y), fg = sigap(vf.y), gg = tanhap(vg.y), og = sigap(vo.y);
                cst[2*j+1] = fg*cst[2*j+1] + ig*gg;
                hout[2*j+1] = og * tanhap(cst[2*j+1]);
            }
        }
        {
            float* hdst = g_h + (((size_t)d*L_ + t)*B_ + q8*8)*H_ + hb + hl;
            #pragma unroll
            for (int k = 0; k < 8; k++) hdst[(size_t)k*H_] = hout[k];
        }
        __syncthreads();
        if (tid == 0) {
            __threadfence();
            st_release(my_cnt, s + 1);
        }
    }
}

// ---------------- emission GEMM (unchanged) ----------------
__global__ __launch_bounds__(768) void k_emit(const float* __restrict__ Wem,
                                              const float* __restrict__ bem)
{
    extern __shared__ float smc[];
    float* Hcat = smc;            // [64][520]
    float* Wsm  = smc + 64*520;   // [12][516]
    int l   = blockIdx.x;
    int tid = threadIdx.x;
    const float4* hf  = (const float4*)(g_h + ((size_t)0*L_ + l)*B_*H_);
    const float4* hbk = (const float4*)(g_h + ((size_t)1*L_ + l)*B_*H_);
    for (int e = tid; e < 4096; e += 768) {
        int r = e >> 6, kq = e & 63;
        ((float4*)(Hcat + r*520))[kq]       = hf[e];
        ((float4*)(Hcat + r*520 + 256))[kq] = hbk[e];
    }
    for (int e = tid; e < 12*512; e += 768)
        Wsm[(e >> 9)*516 + (e & 511)] = Wem[e];
    __syncthreads();

    int b = tid / 12, tg = tid - b*12;
    float acc = bem[tg];
    const float4* hrow = (const float4*)(Hcat + b*520);
    const float4* wrow = (const float4*)(Wsm + tg*516);
    #pragma unroll 8
    for (int k4 = 0; k4 < 128; k4++) {
        float4 x = hrow[k4]; float4 w = wrow[k4];
        acc += w.x*x.x + w.y*x.y + w.z*x.z + w.w*x.w;
    }
    g_emit[((size_t)l*B_ + b)*T_ + tg] = acc;
}

// ---------------- CRF NLL (unchanged) ----------------
__global__ void k_crf(const int* __restrict__ tags, const float* __restrict__ trans)
{
    int b = blockIdx.x;
    int lane = threadIdx.x;
    __shared__ float tr[T_*T_];
    for (int i = lane; i < T_*T_; i += 32) tr[i] = trans[i];
    __syncwarp();
    const unsigned FULL = 0xffffffffu;
    int mylane = (lane < T_) ? lane : 0;
    float alpha = (lane < T_) ? g_emit[(size_t)b*T_ + lane] : 0.f;
    for (int l = 1; l < L_; l++) {
        float v[T_];
        float m = -1e30f;
        #pragma unroll
        for (int t2 = 0; t2 < T_; t2++) {
            float at = __shfl_sync(FULL, alpha, t2);
            float vv = at + tr[t2*T_ + mylane];
            v[t2] = vv;
            m = fmaxf(m, vv);
        }
        float ssum = 0.f;
        #pragma unroll
        for (int t2 = 0; t2 < T_; t2++) ssum += __expf(v[t2] - m);
        float e = (lane < T_) ? g_emit[((size_t)l*B_ + b)*T_ + lane] : 0.f;
        alpha = m + __logf(ssum) + e;
    }
    float am = (lane < T_) ? alpha : -1e30f;
    float mm = am;
    for (int o = 16; o; o >>= 1) mm = fmaxf(mm, __shfl_xor_sync(FULL, mm, o));
    float es = (lane < T_) ? __expf(alpha - mm) : 0.f;
    for (int o = 16; o; o >>= 1) es += __shfl_xor_sync(FULL, es, o);
    float logZ = mm + __logf(es);

    float eg = 0.f, tg2 = 0.f;
    for (int l = lane; l < L_; l += 32) {
        int tv = tags[b*L_ + l];
        eg += g_emit[((size_t)l*B_ + b)*T_ + tv];
    }
    for (int l = lane; l < L_-1; l += 32) {
        int t0v = tags[b*L_ + l], t1v = tags[b*L_ + l + 1];
        tg2 += tr[t0v*T_ + t1v];
    }
    for (int o = 16; o; o >>= 1) {
        eg  += __shfl_xor_sync(FULL, eg,  o);
        tg2 += __shfl_xor_sync(FULL, tg2, o);
    }
    if (lane == 0) g_nll[b] = logZ - eg - tg2;
}

__global__ void k_mean(float* out)
{
    if (threadIdx.x == 0) {
        float s = 0.f;
        for (int i = 0; i < B_; i++) s += g_nll[i];
        out[0] = s / (float)B_;
    }
}

// ---------------- launch ----------------
extern "C" void kernel_launch(void* const* d_in, const int* in_sizes, int n_in,
                              void* d_out, int out_size)
{
    const int*   sent  = (const int*)  d_in[0];
    const int*   tags  = (const int*)  d_in[1];
    const float* emb   = (const float*)d_in[2];
    const float* Wihf  = (const float*)d_in[3];
    const float* Whhf  = (const float*)d_in[4];
    const float* bf    = (const float*)d_in[5];
    const float* Wihb  = (const float*)d_in[6];
    const float* Whhb  = (const float*)d_in[7];
    const float* bb    = (const float*)d_in[8];
    const float* Wem   = (const float*)d_in[9];
    const float* bem   = (const float*)d_in[10];
    const float* trans = (const float*)d_in[11];
    float* out = (float*)d_out;

    cudaFuncSetAttribute(k_ingate, cudaFuncAttributeMaxDynamicSharedMemorySize, 64*256*4);
    cudaFuncSetAttribute(k_lstm,   cudaFuncAttributeMaxDynamicSharedMemorySize, LSTM_SMEM);
    cudaFuncSetAttribute(k_emit,   cudaFuncAttributeMaxDynamicSharedMemorySize, (64*520 + 12*516)*4);

    k_reset<<<1, 32>>>();
    dim3 gA(L_, 8);
    k_ingate<<<gA, 256, 64*256*4>>>(sent, emb, Wihf, bf, Wihb, bb);
    k_lstm<<<16, 256, LSTM_SMEM>>>(Whhf, Whhb);
    k_emit<<<L_, 768, (64*520 + 12*516)*4>>>(Wem, bem);
    k_crf<<<B_, 32>>>(tags, trans);
    k_mean<<<1, 32>>>(out);
}

// round 6
// speedup vs baseline: 1.4444x; 1.4444x over previous
#include <cuda_runtime.h>
#include <cuda_bf16.h>
#include <math.h>
#include <cstdint>

#define L_ 512
#define B_ 64
#define E_ 256
#define H_ 256
#define T_ 12

typedef unsigned long long u64;

// ---------------- helpers ----------------
__device__ __forceinline__ u64 fma2(u64 a, u64 b, u64 c) {
    u64 d;
    asm("fma.rn.f32x2 %0, %1, %2, %3;" : "=l"(d) : "l"(a), "l"(b), "l"(c));
    return d;
}
__device__ __forceinline__ float2 unpack2(u64 v) {
    float2 r;
    asm("mov.b64 {%0, %1}, %2;" : "=f"(r.x), "=f"(r.y) : "l"(v));
    return r;
}
__device__ __forceinline__ float tanhap(float x) {
    float y;
    asm("tanh.approx.f32 %0, %1;" : "=f"(y) : "f"(x));
    return y;
}
__device__ __forceinline__ float sigap(float x) {
    return fmaf(0.5f, tanhap(0.5f * x), 0.5f);
}
__device__ __forceinline__ uint32_t smem_u32(const void* p) {
    uint32_t a;
    asm("{ .reg .u64 t; cvta.to.shared.u64 t, %1; cvt.u32.u64 %0, t; }" : "=r"(a) : "l"(p));
    return a;
}
__device__ __forceinline__ uint32_t packbf(float lo, float hi) {
    uint32_t r;
    asm("cvt.rn.bf16x2.f32 %0, %1, %2;" : "=r"(r) : "f"(hi), "f"(lo));
    return r;
}
__device__ __forceinline__ void ldsm_x4(uint32_t& r0, uint32_t& r1, uint32_t& r2, uint32_t& r3, uint32_t addr) {
    asm volatile("ldmatrix.sync.aligned.m8n8.x4.shared.b16 {%0,%1,%2,%3}, [%4];"
        : "=r"(r0), "=r"(r1), "=r"(r2), "=r"(r3) : "r"(addr));
}
__device__ __forceinline__ void mma16816(float& d0, float& d1, float& d2, float& d3,
                                         uint32_t a0, uint32_t a1, uint32_t a2, uint32_t a3,
                                         uint32_t b0, uint32_t b1) {
    asm volatile("mma.sync.aligned.m16n8k16.row.col.f32.bf16.bf16.f32 "
        "{%0,%1,%2,%3}, {%4,%5,%6,%7}, {%8,%9}, {%0,%1,%2,%3};"
        : "+f"(d0), "+f"(d1), "+f"(d2), "+f"(d3)
        : "r"(a0), "r"(a1), "r"(a2), "r"(a3), "r"(b0), "r"(b1));
}
__device__ __forceinline__ uint32_t mapa_rank(uint32_t local, uint32_t rank) {
    uint32_t r;
    asm("mapa.shared::cluster.u32 %0, %1, %2;" : "=r"(r) : "r"(local), "r"(rank));
    return r;
}
__device__ __forceinline__ void mbar_arrive_remote(uint32_t remAddr) {
    asm volatile("mbarrier.arrive.release.cluster.shared::cluster.b64 _, [%0];"
                 :: "r"(remAddr) : "memory");
}
__device__ __forceinline__ void mbar_wait_cluster(uint32_t mbar, uint32_t parity) {
    uint32_t done = 0;
    while (!done) {
        asm volatile(
            "{\n\t.reg .pred p;\n\t"
            "mbarrier.try_wait.parity.acquire.cluster.shared::cta.b64 p, [%1], %2, 0x989680;\n\t"
            "selp.b32 %0, 1, 0, p;\n\t}"
            : "=r"(done) : "r"(mbar), "r"(parity) : "memory");
    }
}

// ---------------- scratch ----------------
__device__ float g_gx[(size_t)2*L_*B_*1024];          // input gates (incl bias)
__device__ float g_h [(size_t)2*L_*B_*H_];            // hidden fp32 (for k_emit)
__device__ __nv_bfloat16 g_hb[(size_t)2*L_*B_*H_];    // hidden bf16 (for recurrence)
__device__ float g_emit[(size_t)L_*B_*T_];
__device__ float g_nll[B_];

// ---------------- input-gate GEMM (f32x2 packed, unchanged) ----------------
__global__ __launch_bounds__(256, 1) void k_ingate(
    const int* __restrict__ sent, const float* __restrict__ emb,
    const float* __restrict__ Wf, const float* __restrict__ bfv,
    const float* __restrict__ Wb, const float* __restrict__ bbv)
{
    extern __shared__ float Xs[];
    __shared__ int tok[B_];
    int l   = blockIdx.x;
    int tid = threadIdx.x;
    if (tid < B_) tok[tid] = sent[tid*L_ + l];
    __syncthreads();
    float4* Xs4 = (float4*)Xs;
    #pragma unroll
    for (int i = 0; i < 16; i++) {
        int e = i*256 + tid;
        int r = e >> 6, kq = e & 63;
        Xs4[e] = ((const float4*)emb)[(size_t)tok[r]*64 + kq];
    }
    __syncthreads();

    int j   = blockIdx.y*256 + tid;
    int dir = j >> 10, jj = j & 1023;
    const float* W = dir ? Wb : Wf;
    const ulonglong2* W2 = (const ulonglong2*)(W + (size_t)jj*256);
    const ulonglong2* X2 = (const ulonglong2*)Xs;

    u64 acc2[64];
    #pragma unroll
    for (int r = 0; r < 64; r++) acc2[r] = 0ull;

    #pragma unroll 1
    for (int k4 = 0; k4 < 64; k4++) {
        ulonglong2 w = W2[k4];
        #pragma unroll
        for (int r = 0; r < 64; r++) {
            ulonglong2 x = X2[r*64 + k4];
            acc2[r] = fma2(w.x, x.x, acc2[r]);
            acc2[r] = fma2(w.y, x.y, acc2[r]);
        }
    }
    float bias = (dir ? bbv : bfv)[jj];
    float* outp = g_gx + (((size_t)dir*L_ + l)*B_)*1024 + jj;
    #pragma unroll
    for (int r = 0; r < 64; r++) {
        float2 p = unpack2(acc2[r]);
        outp[(size_t)r*1024] = p.x + p.y + bias;
    }
}

// ---------------- persistent LSTM recurrence: mma.sync + cluster mbarrier sync ----------------
// grid 16, cluster 8. dir = blockIdx.x>>3, rank p = cluster_ctarank, CTA owns hids [32p,32p+32).
// Per step: wait mbar -> stage h(bf16) from L2 -> MMA D[128,64] -> Ps(gx prefilled) += D
//           -> activations -> h out (fp32 + bf16) -> remote mbarrier arrives to 8 peers.
static const int BS_PITCH_B = 528;               // 264 halves per row
static const int SM_PS      = 64 * BS_PITCH_B;   // 33792
static const int SM_MBAR    = SM_PS + 128*66*4;  // 67584
static const int LSTM_SMEM  = SM_MBAR + 128;     // barriers + pad

__global__ __launch_bounds__(256, 1) __cluster_dims__(8, 1, 1)
void k_lstm(const float* __restrict__ Whf, const float* __restrict__ Whb)
{
    extern __shared__ __align__(1024) char sm[];
    float* Ps = (float*)(sm + SM_PS);
    uint32_t smb = smem_u32(sm);
    int d = blockIdx.x >> 3;
    uint32_t p;
    asm("mov.u32 %0, %%cluster_ctarank;" : "=r"(p));
    int hb = (int)p * 32;
    int tid = threadIdx.x;
    int w = tid >> 5, l = tid & 31;
    const float* W = d ? Whb : Whf;

    // ---- mbarrier init (2 alternating barriers, 8 arrivals each) ----
    if (tid == 0) {
        asm volatile("mbarrier.init.shared.b64 [%0], %1;" :: "r"(smb + SM_MBAR),     "r"(8u) : "memory");
        asm volatile("mbarrier.init.shared.b64 [%0], %1;" :: "r"(smb + SM_MBAR + 8), "r"(8u) : "memory");
    }
    __syncthreads();
    asm volatile("barrier.cluster.arrive.aligned;" ::: "memory");
    asm volatile("barrier.cluster.wait.aligned;" ::: "memory");

    // ---- A fragments (static W) in registers ----
    int r0 = 16*w + (l >> 2), r1 = r0 + 8;
    const float* wr0 = W + (size_t)((r0 >> 5)*H_ + hb + (r0 & 31))*H_;
    const float* wr1 = W + (size_t)((r1 >> 5)*H_ + hb + (r1 & 31))*H_;
    uint32_t A0[16], A1[16], A2[16], A3[16];
    {
        int kc0 = (l & 3)*2;
        #pragma unroll
        for (int kt = 0; kt < 16; kt++) {
            int kc = kt*16 + kc0;
            A0[kt] = packbf(wr0[kc],   wr0[kc+1]);
            A1[kt] = packbf(wr1[kc],   wr1[kc+1]);
            A2[kt] = packbf(wr0[kc+8], wr0[kc+9]);
            A3[kt] = packbf(wr1[kc+8], wr1[kc+9]);
        }
    }

    // ldmatrix per-lane row base addresses
    uint32_t rowa[8];
    {
        int lrow = l & 7, grp = l >> 3;
        #pragma unroll
        for (int nt = 0; nt < 8; nt++)
            rowa[nt] = smb + (uint32_t)((nt*8 + lrow)*BS_PITCH_B + grp*16);
    }

    // gx mapping
    int rr  = tid & 127;
    int bb0 = (tid >> 7) * 32;
    int goff = (rr >> 5)*256 + hb + (rr & 31);

    // phase-B mapping
    int hl = tid & 31, q8 = tid >> 5;
    float cst[8];
    #pragma unroll
    for (int k = 0; k < 8; k++) cst[k] = 0.f;

    // remote barrier addresses for this producer thread (tid<8 -> peer rank tid)
    uint32_t rem0 = 0, rem1 = 0;
    if (tid < 8) {
        rem0 = mapa_rank(smb + SM_MBAR,     (uint32_t)tid);
        rem1 = mapa_rank(smb + SM_MBAR + 8, (uint32_t)tid);
    }

    for (int s = 0; s < L_; s++) {
        int t = d ? (L_-1-s) : s;

        // ---- gx prefetch into registers (independent of h) ----
        float gxv[32];
        {
            const float* gxt = g_gx + ((size_t)(d*L_ + t)*B_)*1024 + goff;
            #pragma unroll
            for (int j = 0; j < 32; j++) gxv[j] = gxt[(size_t)(bb0 + j)*1024];
        }

        // ---- wait + stage h (bf16 copy) ----
        if (s == 0) {
            for (int i = tid; i < SM_PS/4; i += 256) ((uint32_t*)sm)[i] = 0;
        } else {
            int sp = s - 1;
            mbar_wait_cluster(smb + SM_MBAR + (sp & 1)*8, (uint32_t)((sp >> 1) & 1));
            int tprev = d ? (t+1) : (t-1);
            const uint4* hsrc = (const uint4*)(g_hb + (((size_t)d*L_ + tprev)*B_)*H_);
            #pragma unroll
            for (int i = 0; i < 8; i++) {
                int idx = i*256 + tid;
                int b = idx >> 5, kq = idx & 31;
                *(uint4*)(sm + b*BS_PITCH_B + kq*16) = hsrc[idx];
            }
        }

        // ---- gx -> Ps ----
        {
            float* prow = Ps + rr*66 + bb0;
            #pragma unroll
            for (int j = 0; j < 32; j++) prow[j] = gxv[j];
        }
        __syncthreads();

        // ---- MMA mainloop ----
        float acc[8][4];
        #pragma unroll
        for (int nt = 0; nt < 8; nt++)
            #pragma unroll
            for (int k = 0; k < 4; k++) acc[nt][k] = 0.f;

        #pragma unroll
        for (int ktp = 0; ktp < 8; ktp++) {
            #pragma unroll
            for (int nt = 0; nt < 8; nt++) {
                uint32_t b0, b1, b2, b3;
                ldsm_x4(b0, b1, b2, b3, rowa[nt] + ktp*64);
                mma16816(acc[nt][0], acc[nt][1], acc[nt][2], acc[nt][3],
                         A0[2*ktp], A1[2*ktp], A2[2*ktp], A3[2*ktp], b0, b1);
                mma16816(acc[nt][0], acc[nt][1], acc[nt][2], acc[nt][3],
                         A0[2*ktp+1], A1[2*ktp+1], A2[2*ktp+1], A3[2*ktp+1], b2, b3);
            }
        }

        // ---- Ps += D ----
        {
            int cc = (l & 3)*2;
            #pragma unroll
            for (int nt = 0; nt < 8; nt++) {
                float2* p0 = (float2*)(Ps + r0*66 + nt*8 + cc);
                float2 v0 = *p0; v0.x += acc[nt][0]; v0.y += acc[nt][1]; *p0 = v0;
                float2* p1 = (float2*)(Ps + r1*66 + nt*8 + cc);
                float2 v1 = *p1; v1.x += acc[nt][2]; v1.y += acc[nt][3]; *p1 = v1;
            }
        }
        __syncthreads();

        // ---- phase B: activations, c update, h out ----
        float hout[8];
        #pragma unroll
        for (int j = 0; j < 4; j++) {
            float2 vi = *(const float2*)(Ps + ( 0 + hl)*66 + q8*8 + 2*j);
            float2 vf = *(const float2*)(Ps + (32 + hl)*66 + q8*8 + 2*j);
            float2 vg = *(const float2*)(Ps + (64 + hl)*66 + q8*8 + 2*j);
            float2 vo = *(const float2*)(Ps + (96 + hl)*66 + q8*8 + 2*j);
            {
                float ig = sigap(vi.x), fg = sigap(vf.x), gg = tanhap(vg.x), og = sigap(vo.x);
                cst[2*j] = fg*cst[2*j] + ig*gg;
                hout[2*j] = og * tanhap(cst[2*j]);
            }
            {
                float ig = sigap(vi.y), fg = sigap(vf.y), gg = tanhap(vg.y), og = sigap(vo.y);
                cst[2*j+1] = fg*cst[2*j+1] + ig*gg;
                hout[2*j+1] = og * tanhap(cst[2*j+1]);
            }
        }
        {
            float* hdst = g_h + (((size_t)d*L_ + t)*B_ + q8*8)*H_ + hb + hl;
            __nv_bfloat16* hbd = g_hb + (((size_t)d*L_ + t)*B_ + q8*8)*H_ + hb + hl;
            #pragma unroll
            for (int k = 0; k < 8; k++) {
                hdst[(size_t)k*H_] = hout[k];
                hbd [(size_t)k*H_] = __float2bfloat16(hout[k]);
            }
        }
        __syncthreads();
        if (tid < 8 && s < L_-1) {
            mbar_arrive_remote((s & 1) ? rem1 : rem0);
        }
    }
}

// ---------------- emission GEMM (unchanged) ----------------
__global__ __launch_bounds__(768) void k_emit(const float* __restrict__ Wem,
                                              const float* __restrict__ bem)
{
    extern __shared__ float smc[];
    float* Hcat = smc;            // [64][520]
    float* Wsm  = smc + 64*520;   // [12][516]
    int l   = blockIdx.x;
    int tid = threadIdx.x;
    const float4* hf  = (const float4*)(g_h + ((size_t)0*L_ + l)*B_*H_);
    const float4* hbk = (const float4*)(g_h + ((size_t)1*L_ + l)*B_*H_);
    for (int e = tid; e < 4096; e += 768) {
        int r = e >> 6, kq = e & 63;
        ((float4*)(Hcat + r*520))[kq]       = hf[e];
        ((float4*)(Hcat + r*520 + 256))[kq] = hbk[e];
    }
    for (int e = tid; e < 12*512; e += 768)
        Wsm[(e >> 9)*516 + (e & 511)] = Wem[e];
    __syncthreads();

    int b = tid / 12, tg = tid - b*12;
    float acc = bem[tg];
    const float4* hrow = (const float4*)(Hcat + b*520);
    const float4* wrow = (const float4*)(Wsm + tg*516);
    #pragma unroll 8
    for (int k4 = 0; k4 < 128; k4++) {
        float4 x = hrow[k4]; float4 w = wrow[k4];
        acc += w.x*x.x + w.y*x.y + w.z*x.z + w.w*x.w;
    }
    g_emit[((size_t)l*B_ + b)*T_ + tg] = acc;
}

// ---------------- CRF NLL (unchanged) ----------------
__global__ void k_crf(const int* __restrict__ tags, const float* __restrict__ trans)
{
    int b = blockIdx.x;
    int lane = threadIdx.x;
    __shared__ float tr[T_*T_];
    for (int i = lane; i < T_*T_; i += 32) tr[i] = trans[i];
    __syncwarp();
    const unsigned FULL = 0xffffffffu;
    int mylane = (lane < T_) ? lane : 0;
    float alpha = (lane < T_) ? g_emit[(size_t)b*T_ + lane] : 0.f;
    for (int l = 1; l < L_; l++) {
        float v[T_];
        float m = -1e30f;
        #pragma unroll
        for (int t2 = 0; t2 < T_; t2++) {
            float at = __shfl_sync(FULL, alpha, t2);
            float vv = at + tr[t2*T_ + mylane];
            v[t2] = vv;
            m = fmaxf(m, vv);
        }
        float ssum = 0.f;
        #pragma unroll
        for (int t2 = 0; t2 < T_; t2++) ssum += __expf(v[t2] - m);
        float e = (lane < T_) ? g_emit[((size_t)l*B_ + b)*T_ + lane] : 0.f;
        alpha = m + __logf(ssum) + e;
    }
    float am = (lane < T_) ? alpha : -1e30f;
    float mm = am;
    for (int o = 16; o; o >>= 1) mm = fmaxf(mm, __shfl_xor_sync(FULL, mm, o));
    float es = (lane < T_) ? __expf(alpha - mm) : 0.f;
    for (int o = 16; o; o >>= 1) es += __shfl_xor_sync(FULL, es, o);
    float logZ = mm + __logf(es);

    float eg = 0.f, tg2 = 0.f;
    for (int l = lane; l < L_; l += 32) {
        int tv = tags[b*L_ + l];
        eg += g_emit[((size_t)l*B_ + b)*T_ + tv];
    }
    for (int l = lane; l < L_-1; l += 32) {
        int t0v = tags[b*L_ + l], t1v = tags[b*L_ + l + 1];
        tg2 += tr[t0v*T_ + t1v];
    }
    for (int o = 16; o; o >>= 1) {
        eg  += __shfl_xor_sync(FULL, eg,  o);
        tg2 += __shfl_xor_sync(FULL, tg2, o);
    }
    if (lane == 0) g_nll[b] = logZ - eg - tg2;
}

__global__ void k_mean(float* out)
{
    if (threadIdx.x == 0) {
        float s = 0.f;
        for (int i = 0; i < B_; i++) s += g_nll[i];
        out[0] = s / (float)B_;
    }
}

// ---------------- launch ----------------
extern "C" void kernel_launch(void* const* d_in, const int* in_sizes, int n_in,
                              void* d_out, int out_size)
{
    const int*   sent  = (const int*)  d_in[0];
    const int*   tags  = (const int*)  d_in[1];
    const float* emb   = (const float*)d_in[2];
    const float* Wihf  = (const float*)d_in[3];
    const float* Whhf  = (const float*)d_in[4];
    const float* bf    = (const float*)d_in[5];
    const float* Wihb  = (const float*)d_in[6];
    const float* Whhb  = (const float*)d_in[7];
    const float* bb    = (const float*)d_in[8];
    const float* Wem   = (const float*)d_in[9];
    const float* bem   = (const float*)d_in[10];
    const float* trans = (const float*)d_in[11];
    float* out = (float*)d_out;

    cudaFuncSetAttribute(k_ingate, cudaFuncAttributeMaxDynamicSharedMemorySize, 64*256*4);
    cudaFuncSetAttribute(k_lstm,   cudaFuncAttributeMaxDynamicSharedMemorySize, LSTM_SMEM);
    cudaFuncSetAttribute(k_emit,   cudaFuncAttributeMaxDynamicSharedMemorySize, (64*520 + 12*516)*4);

    dim3 gA(L_, 8);
    k_ingate<<<gA, 256, 64*256*4>>>(sent, emb, Wihf, bf, Wihb, bb);
    k_lstm<<<16, 256, LSTM_SMEM>>>(Whhf, Whhb);
    k_emit<<<L_, 768, (64*520 + 12*516)*4>>>(Wem, bem);
    k_crf<<<B_, 32>>>(tags, trans);
    k_mean<<<1, 32>>>(out);
}

// round 8
// speedup vs baseline: 1.8124x; 1.2547x over previous
#include <cuda_runtime.h>
#include <cuda_bf16.h>
#include <math.h>
#include <cstdint>

#define L_ 512
#define B_ 64
#define E_ 256
#define H_ 256
#define T_ 12
#define CS 8    // cluster size (verified working)

typedef unsigned long long u64;

// ---------------- helpers ----------------
__device__ __forceinline__ u64 fma2(u64 a, u64 b, u64 c) {
    u64 d;
    asm("fma.rn.f32x2 %0, %1, %2, %3;" : "=l"(d) : "l"(a), "l"(b), "l"(c));
    return d;
}
__device__ __forceinline__ float2 unpack2(u64 v) {
    float2 r;
    asm("mov.b64 {%0, %1}, %2;" : "=f"(r.x), "=f"(r.y) : "l"(v));
    return r;
}
__device__ __forceinline__ float tanhap(float x) {
    float y;
    asm("tanh.approx.f32 %0, %1;" : "=f"(y) : "f"(x));
    return y;
}
__device__ __forceinline__ float sigap(float x) {
    return fmaf(0.5f, tanhap(0.5f * x), 0.5f);
}
__device__ __forceinline__ uint32_t smem_u32(const void* p) {
    uint32_t a;
    asm("{ .reg .u64 t; cvta.to.shared.u64 t, %1; cvt.u32.u64 %0, t; }" : "=r"(a) : "l"(p));
    return a;
}
__device__ __forceinline__ uint32_t packbf(float lo, float hi) {
    uint32_t r;
    asm("cvt.rn.bf16x2.f32 %0, %1, %2;" : "=r"(r) : "f"(hi), "f"(lo));
    return r;
}
__device__ __forceinline__ void ldsm_x4(uint32_t& r0, uint32_t& r1, uint32_t& r2, uint32_t& r3, uint32_t addr) {
    asm volatile("ldmatrix.sync.aligned.m8n8.x4.shared.b16 {%0,%1,%2,%3}, [%4];"
        : "=r"(r0), "=r"(r1), "=r"(r2), "=r"(r3) : "r"(addr));
}
__device__ __forceinline__ void mma16816(float& d0, float& d1, float& d2, float& d3,
                                         uint32_t a0, uint32_t a1, uint32_t a2, uint32_t a3,
                                         uint32_t b0, uint32_t b1) {
    asm volatile("mma.sync.aligned.m16n8k16.row.col.f32.bf16.bf16.f32 "
        "{%0,%1,%2,%3}, {%4,%5,%6,%7}, {%8,%9}, {%0,%1,%2,%3};"
        : "+f"(d0), "+f"(d1), "+f"(d2), "+f"(d3)
        : "r"(a0), "r"(a1), "r"(a2), "r"(a3), "r"(b0), "r"(b1));
}
__device__ __forceinline__ uint32_t mapa_rank(uint32_t local, uint32_t rank) {
    uint32_t r;
    asm("mapa.shared::cluster.u32 %0, %1, %2;" : "=r"(r) : "r"(local), "r"(rank));
    return r;
}
__device__ __forceinline__ void mbar_arrive_remote(uint32_t remAddr) {
    asm volatile("mbarrier.arrive.release.cluster.shared::cluster.b64 _, [%0];"
                 :: "r"(remAddr) : "memory");
}
__device__ __forceinline__ void mbar_wait_cluster(uint32_t mbar, uint32_t parity) {
    uint32_t done = 0;
    while (!done) {
        asm volatile(
            "{\n\t.reg .pred p;\n\t"
            "mbarrier.try_wait.parity.acquire.cluster.shared::cta.b64 p, [%1], %2, 0x989680;\n\t"
            "selp.b32 %0, 1, 0, p;\n\t}"
            : "=r"(done) : "r"(mbar), "r"(parity) : "memory");
    }
}

// ---------------- scratch ----------------
__device__ float g_gx[(size_t)2*L_*1024*B_];          // input gates TRANSPOSED: [2][L][gate-row j][b]
__device__ __nv_bfloat16 g_hb[(size_t)2*L_*B_*H_];    // hidden bf16
__device__ float g_emit[(size_t)L_*B_*T_];
__device__ float g_nll[B_];

// ---------------- input-gate GEMM (f32x2 packed; transposed store) ----------------
__global__ __launch_bounds__(256, 1) void k_ingate(
    const int* __restrict__ sent, const float* __restrict__ emb,
    const float* __restrict__ Wf, const float* __restrict__ bfv,
    const float* __restrict__ Wb, const float* __restrict__ bbv)
{
    extern __shared__ float Xs[];
    __shared__ int tok[B_];
    int l   = blockIdx.x;
    int tid = threadIdx.x;
    if (tid < B_) tok[tid] = sent[tid*L_ + l];
    __syncthreads();
    float4* Xs4 = (float4*)Xs;
    #pragma unroll
    for (int i = 0; i < 16; i++) {
        int e = i*256 + tid;
        int r = e >> 6, kq = e & 63;
        Xs4[e] = ((const float4*)emb)[(size_t)tok[r]*64 + kq];
    }
    __syncthreads();

    int j   = blockIdx.y*256 + tid;
    int dir = j >> 10, jj = j & 1023;
    const float* W = dir ? Wb : Wf;
    const ulonglong2* W2 = (const ulonglong2*)(W + (size_t)jj*256);
    const ulonglong2* X2 = (const ulonglong2*)Xs;

    u64 acc2[64];
    #pragma unroll
    for (int r = 0; r < 64; r++) acc2[r] = 0ull;

    #pragma unroll 1
    for (int k4 = 0; k4 < 64; k4++) {
        ulonglong2 w = W2[k4];
        #pragma unroll
        for (int r = 0; r < 64; r++) {
            ulonglong2 x = X2[r*64 + k4];
            acc2[r] = fma2(w.x, x.x, acc2[r]);
            acc2[r] = fma2(w.y, x.y, acc2[r]);
        }
    }
    float bias = (dir ? bbv : bfv)[jj];
    // transposed: [d][l][jj][b] -> thread writes 64 contiguous floats
    float* outp = g_gx + ((size_t)(dir*L_ + l)*1024 + jj)*64;
    #pragma unroll
    for (int r4 = 0; r4 < 16; r4++) {
        float2 pa = unpack2(acc2[4*r4+0]);
        float2 pb = unpack2(acc2[4*r4+1]);
        float2 pc = unpack2(acc2[4*r4+2]);
        float2 pd = unpack2(acc2[4*r4+3]);
        *(float4*)(outp + 4*r4) = make_float4(pa.x+pa.y+bias, pb.x+pb.y+bias,
                                              pc.x+pc.y+bias, pd.x+pd.y+bias);
    }
}

// ---------------- persistent LSTM recurrence: mma.sync, 4 independent clusters of 8 ----------------
// 32 CTAs = (dir 2) x (batch-half 2) x (rank 8). CTA owns hids [32p,32p+32), batches [32g,32g+32).
// D[128 gate-rows, 32 batch] = W_local[128,256] x h_half[32,256]^T
static const int BS_PITCH_B = 528;                    // 264 halves per row
static const int SM_PS      = 32 * BS_PITCH_B;        // 16896 (B tile: 32 rows)
static const int PS_PITCH   = 34;                     // floats per Ps row
static const int SM_MBAR    = SM_PS + 128*PS_PITCH*4; // 16896 + 17408 = 34304
static const int LSTM_SMEM  = SM_MBAR + 128;

__global__ __launch_bounds__(256, 1) __cluster_dims__(CS, 1, 1)
void k_lstm(const float* __restrict__ Whf, const float* __restrict__ Whb)
{
    extern __shared__ __align__(1024) char sm[];
    float* Ps = (float*)(sm + SM_PS);
    uint32_t smb = smem_u32(sm);
    int d = blockIdx.x >> 4;              // direction
    int g = (blockIdx.x >> 3) & 1;        // batch half
    uint32_t p;
    asm("mov.u32 %0, %%cluster_ctarank;" : "=r"(p));
    int hb = (int)p * 32;
    int tid = threadIdx.x;
    int w = tid >> 5, l = tid & 31;
    const float* W = d ? Whb : Whf;

    if (tid == 0) {
        asm volatile("mbarrier.init.shared.b64 [%0], %1;" :: "r"(smb + SM_MBAR),     "r"((uint32_t)CS) : "memory");
        asm volatile("mbarrier.init.shared.b64 [%0], %1;" :: "r"(smb + SM_MBAR + 8), "r"((uint32_t)CS) : "memory");
    }
    __syncthreads();
    asm volatile("barrier.cluster.arrive.aligned;" ::: "memory");
    asm volatile("barrier.cluster.wait.aligned;" ::: "memory");

    // ---- A fragments: warp w -> m-rows [16w,16w+16), all 32 n ----
    int r0 = 16*w + (l >> 2), r1 = r0 + 8;
    const float* wr0 = W + (size_t)((r0 >> 5)*H_ + hb + (r0 & 31))*H_;
    const float* wr1 = W + (size_t)((r1 >> 5)*H_ + hb + (r1 & 31))*H_;
    uint32_t A0[16], A1[16], A2[16], A3[16];
    {
        int kc0 = (l & 3)*2;
        #pragma unroll
        for (int kt = 0; kt < 16; kt++) {
            int kc = kt*16 + kc0;
            A0[kt] = packbf(wr0[kc],   wr0[kc+1]);
            A1[kt] = packbf(wr1[kc],   wr1[kc+1]);
            A2[kt] = packbf(wr0[kc+8], wr0[kc+9]);
            A3[kt] = packbf(wr1[kc+8], wr1[kc+9]);
        }
    }

    // ldmatrix per-lane row base addresses (4 n-tiles of 8 local batches)
    uint32_t rowa[4];
    {
        int lrow = l & 7, grp = l >> 3;
        #pragma unroll
        for (int nt = 0; nt < 4; nt++)
            rowa[nt] = smb + (uint32_t)((nt*8 + lrow)*BS_PITCH_B + grp*16);
    }

    // gx mapping: rr = gate-row 0..127, bb0 = local batch group of 16
    int rr  = tid & 127;
    int bb0 = (tid >> 7) * 16;
    int goff = (rr >> 5)*256 + hb + (rr & 31);

    // phase-B mapping: thread owns (hid hl 0..31, local batches 4q..4q+3)
    int hl = tid & 31, q = tid >> 5;
    float cst[4];
    #pragma unroll
    for (int k = 0; k < 4; k++) cst[k] = 0.f;

    uint32_t rem0 = 0, rem1 = 0;
    if (tid < CS) {
        rem0 = mapa_rank(smb + SM_MBAR,     (uint32_t)tid);
        rem1 = mapa_rank(smb + SM_MBAR + 8, (uint32_t)tid);
    }

    for (int s = 0; s < L_; s++) {
        int t = d ? (L_-1-s) : s;

        // ---- gx prefetch (coalesced, independent of h) ----
        float4 gxv[4];
        {
            const float4* gxt = (const float4*)(g_gx + ((size_t)(d*L_ + t)*1024 + goff)*64 + 32*g + bb0);
            #pragma unroll
            for (int j4 = 0; j4 < 4; j4++) gxv[j4] = gxt[j4];
        }

        // ---- wait + stage h (bf16 copy, this batch half only: 16 KB) ----
        if (s == 0) {
            for (int i = tid; i < SM_PS/4; i += 256) ((uint32_t*)sm)[i] = 0;
        } else {
            int sp = s - 1;
            mbar_wait_cluster(smb + SM_MBAR + (sp & 1)*8, (uint32_t)((sp >> 1) & 1));
            int tprev = d ? (t+1) : (t-1);
            const uint4* hsrc = (const uint4*)(g_hb + (((size_t)d*L_ + tprev)*B_ + 32*g)*H_);
            #pragma unroll
            for (int i = 0; i < 4; i++) {
                int idx = i*256 + tid;
                int b = idx >> 5, kq = idx & 31;
                *(uint4*)(sm + b*BS_PITCH_B + kq*16) = hsrc[idx];
            }
        }

        // ---- gx -> Ps ----
        {
            float2* prow = (float2*)(Ps + rr*PS_PITCH + bb0);
            const float2* gv = (const float2*)gxv;
            #pragma unroll
            for (int j2 = 0; j2 < 8; j2++) prow[j2] = gv[j2];
        }
        __syncthreads();

        // ---- MMA mainloop: D[128,32], warp covers 16 m x 32 n ----
        float acc[4][4];
        #pragma unroll
        for (int nt = 0; nt < 4; nt++)
            #pragma unroll
            for (int k = 0; k < 4; k++) acc[nt][k] = 0.f;

        #pragma unroll
        for (int ktp = 0; ktp < 8; ktp++) {
            #pragma unroll
            for (int nt = 0; nt < 4; nt++) {
                uint32_t b0, b1, b2, b3;
                ldsm_x4(b0, b1, b2, b3, rowa[nt] + ktp*64);
                mma16816(acc[nt][0], acc[nt][1], acc[nt][2], acc[nt][3],
                         A0[2*ktp], A1[2*ktp], A2[2*ktp], A3[2*ktp], b0, b1);
                mma16816(acc[nt][0], acc[nt][1], acc[nt][2], acc[nt][3],
                         A0[2*ktp+1], A1[2*ktp+1], A2[2*ktp+1], A3[2*ktp+1], b2, b3);
            }
        }

        // ---- Ps += D ----
        {
            int cc = (l & 3)*2;
            #pragma unroll
            for (int nt = 0; nt < 4; nt++) {
                float2* p0 = (float2*)(Ps + r0*PS_PITCH + nt*8 + cc);
                float2 v0 = *p0; v0.x += acc[nt][0]; v0.y += acc[nt][1]; *p0 = v0;
                float2* p1 = (float2*)(Ps + r1*PS_PITCH + nt*8 + cc);
                float2 v1 = *p1; v1.x += acc[nt][2]; v1.y += acc[nt][3]; *p1 = v1;
            }
        }
        __syncthreads();

        // ---- phase B: activations, c update, h out (bf16) ----
        float hout[4];
        #pragma unroll
        for (int j = 0; j < 2; j++) {
            float2 vi = *(const float2*)(Ps + (  0 + hl)*PS_PITCH + q*4 + 2*j);
            float2 vf = *(const float2*)(Ps + ( 32 + hl)*PS_PITCH + q*4 + 2*j);
            float2 vg = *(const float2*)(Ps + ( 64 + hl)*PS_PITCH + q*4 + 2*j);
            float2 vo = *(const float2*)(Ps + ( 96 + hl)*PS_PITCH + q*4 + 2*j);
            {
                float ig = sigap(vi.x), fg = sigap(vf.x), gg = tanhap(vg.x), og = sigap(vo.x);
                cst[2*j] = fg*cst[2*j] + ig*gg;
                hout[2*j] = og * tanhap(cst[2*j]);
            }
            {
                float ig = sigap(vi.y), fg = sigap(vf.y), gg = tanhap(vg.y), og = sigap(vo.y);
                cst[2*j+1] = fg*cst[2*j+1] + ig*gg;
                hout[2*j+1] = og * tanhap(cst[2*j+1]);
            }
        }
        {
            __nv_bfloat16* hbd = g_hb + (((size_t)d*L_ + t)*B_ + 32*g + q*4)*H_ + hb + hl;
            #pragma unroll
            for (int k = 0; k < 4; k++) hbd[(size_t)k*H_] = __float2bfloat16(hout[k]);
        }
        __syncthreads();
        if (tid < CS && s < L_-1) {
            mbar_arrive_remote((s & 1) ? rem1 : rem0);
        }
    }
}

// ---------------- emission GEMM (reads bf16 h) ----------------
__global__ __launch_bounds__(768) void k_emit(const float* __restrict__ Wem,
                                              const float* __restrict__ bem)
{
    extern __shared__ float smc[];
    float* Hcat = smc;            // [64][520]
    float* Wsm  = smc + 64*520;   // [12][516]
    int l   = blockIdx.x;
    int tid = threadIdx.x;
    const uint4* hf  = (const uint4*)(g_hb + ((size_t)0*L_ + l)*B_*H_);
    const uint4* hbk = (const uint4*)(g_hb + ((size_t)1*L_ + l)*B_*H_);
    for (int e = tid; e < 2048; e += 768) {
        int r = e >> 5, kq = e & 31;
        uint4 vf = hf[e], vb = hbk[e];
        const __nv_bfloat162* pf = (const __nv_bfloat162*)&vf;
        const __nv_bfloat162* pb = (const __nv_bfloat162*)&vb;
        float* df = Hcat + r*520 + kq*8;
        float* db = Hcat + r*520 + 256 + kq*8;
        #pragma unroll
        for (int qq = 0; qq < 4; qq++) {
            float2 f2 = __bfloat1622float2(pf[qq]);
            float2 b2 = __bfloat1622float2(pb[qq]);
            df[2*qq] = f2.x; df[2*qq+1] = f2.y;
            db[2*qq] = b2.x; db[2*qq+1] = b2.y;
        }
    }
    for (int e = tid; e < 12*512; e += 768)
        Wsm[(e >> 9)*516 + (e & 511)] = Wem[e];
    __syncthreads();

    int b = tid / 12, tg = tid - b*12;
    float acc = bem[tg];
    const float4* hrow = (const float4*)(Hcat + b*520);
    const float4* wrow = (const float4*)(Wsm + tg*516);
    #pragma unroll 8
    for (int k4 = 0; k4 < 128; k4++) {
        float4 x = hrow[k4]; float4 w = wrow[k4];
        acc += w.x*x.x + w.y*x.y + w.z*x.z + w.w*x.w;
    }
    g_emit[((size_t)l*B_ + b)*T_ + tg] = acc;
}

// ---------------- CRF NLL: one warp per b, emissions prefetched 1 step ahead ----------------
__global__ void k_crf(const int* __restrict__ tags, const float* __restrict__ trans)
{
    int b = blockIdx.x;
    int lane = threadIdx.x;
    __shared__ float tr[T_*T_];
    for (int i = lane; i < T_*T_; i += 32) tr[i] = trans[i];
    __syncwarp();
    const unsigned FULL = 0xffffffffu;
    int mylane = (lane < T_) ? lane : 0;
    float trr[T_];
    #pragma unroll
    for (int t2 = 0; t2 < T_; t2++) trr[t2] = tr[t2*T_ + mylane];

    float alpha = (lane < T_) ? g_emit[(size_t)b*T_ + lane] : 0.f;
    float ep = (lane < T_) ? g_emit[((size_t)1*B_ + b)*T_ + lane] : 0.f;
    for (int l = 1; l < L_; l++) {
        float ecur = ep;
        if (l + 1 < L_)
            ep = (lane < T_) ? g_emit[((size_t)(l+1)*B_ + b)*T_ + lane] : 0.f;
        float v[T_];
        float m = -1e30f;
        #pragma unroll
        for (int t2 = 0; t2 < T_; t2++) {
            float at = __shfl_sync(FULL, alpha, t2);
            float vv = at + trr[t2];
            v[t2] = vv;
            m = fmaxf(m, vv);
        }
        float ssum = 0.f;
        #pragma unroll
        for (int t2 = 0; t2 < T_; t2++) ssum += __expf(v[t2] - m);
        alpha = m + __logf(ssum) + ecur;
    }
    float am = (lane < T_) ? alpha : -1e30f;
    float mm = am;
    for (int o = 16; o; o >>= 1) mm = fmaxf(mm, __shfl_xor_sync(FULL, mm, o));
    float es = (lane < T_) ? __expf(alpha - mm) : 0.f;
    for (int o = 16; o; o >>= 1) es += __shfl_xor_sync(FULL, es, o);
    float logZ = mm + __logf(es);

    float eg = 0.f, tg2 = 0.f;
    for (int l = lane; l < L_; l += 32) {
        int tv = tags[b*L_ + l];
        eg += g_emit[((size_t)l*B_ + b)*T_ + tv];
    }
    for (int l = lane; l < L_-1; l += 32) {
        int t0v = tags[b*L_ + l], t1v = tags[b*L_ + l + 1];
        tg2 += tr[t0v*T_ + t1v];
    }
    for (int o = 16; o; o >>= 1) {
        eg  += __shfl_xor_sync(FULL, eg,  o);
        tg2 += __shfl_xor_sync(FULL, tg2, o);
    }
    if (lane == 0) g_nll[b] = logZ - eg - tg2;
}

__global__ void k_mean(float* out)
{
    int lane = threadIdx.x;
    float s = (lane < 32) ? g_nll[lane] + g_nll[lane + 32] : 0.f;
    s += __shfl_xor_sync(0xffffffffu, s, 16);
    s += __shfl_xor_sync(0xffffffffu, s, 8);
    s += __shfl_xor_sync(0xffffffffu, s, 4);
    s += __shfl_xor_sync(0xffffffffu, s, 2);
    s += __shfl_xor_sync(0xffffffffu, s, 1);
    if (lane == 0) out[0] = s / (float)B_;
}

// ---------------- launch ----------------
extern "C" void kernel_launch(void* const* d_in, const int* in_sizes, int n_in,
                              void* d_out, int out_size)
{
    const int*   sent  = (const int*)  d_in[0];
    const int*   tags  = (const int*)  d_in[1];
    const float* emb   = (const float*)d_in[2];
    const float* Wihf  = (const float*)d_in[3];
    const float* Whhf  = (const float*)d_in[4];
    const float* bf    = (const float*)d_in[5];
    const float* Wihb  = (const float*)d_in[6];
    const float* Whhb  = (const float*)d_in[7];
    const float* bb    = (const float*)d_in[8];
    const float* Wem   = (const float*)d_in[9];
    const float* bem   = (const float*)d_in[10];
    const float* trans = (const float*)d_in[11];
    float* out = (float*)d_out;

    cudaFuncSetAttribute(k_ingate, cudaFuncAttributeMaxDynamicSharedMemorySize, 64*256*4);
    cudaFuncSetAttribute(k_lstm,   cudaFuncAttributeMaxDynamicSharedMemorySize, LSTM_SMEM);
    cudaFuncSetAttribute(k_emit,   cudaFuncAttributeMaxDynamicSharedMemorySize, (64*520 + 12*516)*4);

    dim3 gA(L_, 8);
    k_ingate<<<gA, 256, 64*256*4>>>(sent, emb, Wihf, bf, Wihb, bb);
    k_lstm<<<32, 256, LSTM_SMEM>>>(Whhf, Whhb);
    k_emit<<<L_, 768, (64*520 + 12*516)*4>>>(Wem, bem);
    k_crf<<<B_, 32>>>(tags, trans);
    k_mean<<<1, 32>>>(out);
}